// round 14
// baseline (speedup 1.0000x reference)
#include <cuda_runtime.h>
#include <stdint.h>
#include <math.h>

// Problem constants
#define HDIM 128
#define FDIM 64
#define THDIM 384              // 3*H
#define IS3  0.5773502691896258f      // 1/sqrt(3)
#define ISH  0.08838834764831845f     // 1/sqrt(128)
#define SSC  1.6666666666666667f      // 1/0.6

#define MAXN 50000
#define MAXE 400000
#define EBA 8                  // edges per warp-group

typedef unsigned long long ull;

// Scratch (device globals: allocation-free)
__device__ float g_xd  [MAXN * THDIM];
__device__ float g_h1  [MAXN * FDIM];
__device__ float g_xh  [MAXN * THDIM];
__device__ float g_lvec[MAXN * 3 * HDIM];
__device__ int   g_deg [MAXN];
__device__ int   g_cur [MAXN];
__device__ int   g_bsum[256];
__device__ int   g_boff[256];
__device__ int   g_elist[MAXE];
__device__ int   g_js  [MAXE];
__device__ int   g_is  [MAXE];

// ---------------------------------------------------------------------------
// Packed fp32x2 helpers (FFMA2 — ptxas never auto-fuses)
// ---------------------------------------------------------------------------
__device__ __forceinline__ ull pk(float lo, float hi) {
    ull r; asm("mov.b64 %0, {%1, %2};" : "=l"(r) : "f"(lo), "f"(hi)); return r;
}
__device__ __forceinline__ void upk(ull v, float& lo, float& hi) {
    asm("mov.b64 {%0, %1}, %2;" : "=f"(lo), "=f"(hi) : "l"(v));
}
__device__ __forceinline__ void fma2(ull& d, ull a, ull b) {
    asm("fma.rn.f32x2 %0, %1, %2, %0;" : "+l"(d) : "l"(a), "l"(b));
}

// ---------------------------------------------------------------------------
// Utility + CSR build (counting sort by source j)
// ---------------------------------------------------------------------------
__global__ void zero_kernel(float4* __restrict__ p, long n4) {
    long i = (long)blockIdx.x * blockDim.x + threadIdx.x;
    if (i < n4) p[i] = make_float4(0.f, 0.f, 0.f, 0.f);
}
__global__ void zeroi_kernel(int* __restrict__ p, int n) {
    int i = blockIdx.x * blockDim.x + threadIdx.x;
    if (i < n) p[i] = 0;
}
__global__ void hist_kernel(const int* __restrict__ key, int* __restrict__ deg, int E) {
    int e = blockIdx.x * blockDim.x + threadIdx.x;
    if (e < E) atomicAdd(&deg[key[e]], 1);
}
__global__ void scan1_kernel(const int* __restrict__ deg, int* __restrict__ bsum, int Nn) {
    __shared__ int s[256];
    int t = threadIdx.x;
    int idx = blockIdx.x * 256 + t;
    s[t] = (idx < Nn) ? deg[idx] : 0;
    __syncthreads();
#pragma unroll
    for (int d = 128; d > 0; d >>= 1) {
        if (t < d) s[t] += s[t + d];
        __syncthreads();
    }
    if (t == 0) bsum[blockIdx.x] = s[0];
}
__global__ void scan2_kernel(const int* __restrict__ bsum, int* __restrict__ boff, int nb) {
    __shared__ int s[256];
    int t = threadIdx.x;
    s[t] = (t < nb) ? bsum[t] : 0;
    __syncthreads();
#pragma unroll
    for (int d = 1; d < 256; d <<= 1) {
        int v = (t >= d) ? s[t - d] : 0;
        __syncthreads();
        s[t] += v;
        __syncthreads();
    }
    if (t < nb) boff[t] = (t == 0) ? 0 : s[t - 1];
}
__global__ void scan3_kernel(const int* __restrict__ deg, const int* __restrict__ boff,
                             int* __restrict__ cur, int Nn) {
    __shared__ int s[256];
    int t = threadIdx.x;
    int idx = blockIdx.x * 256 + t;
    int v = (idx < Nn) ? deg[idx] : 0;
    s[t] = v;
    __syncthreads();
#pragma unroll
    for (int d = 1; d < 256; d <<= 1) {
        int x = (t >= d) ? s[t - d] : 0;
        __syncthreads();
        s[t] += x;
        __syncthreads();
    }
    if (idx < Nn)
        cur[idx] = boff[blockIdx.x] + s[t] - v;
}
__global__ void fill_kernel(const int* __restrict__ ej, const int* __restrict__ ei,
                            int* __restrict__ cursor, int* __restrict__ elist,
                            int* __restrict__ js, int* __restrict__ is, int E) {
    int e = blockIdx.x * blockDim.x + threadIdx.x;
    if (e < E) {
        int j = ej[e];
        int slot = atomicAdd(&cursor[j], 1);
        elist[slot] = e;
        js[slot] = j;
        is[slot] = ei[e];
    }
}

// ---------------------------------------------------------------------------
// fp32 SGEMM with FFMA2 inner product: C = act(A @ W + bias)
// ---------------------------------------------------------------------------
template<int BM, int BN, int BK, int TM, int TN, int ACT, int HASB>
__global__ void __launch_bounds__(256)
sgemm_kernel(const float* __restrict__ A, const float* __restrict__ W,
             const float* __restrict__ bias, float* __restrict__ C,
             int M, int N, int K)
{
    __shared__ float As[BK][BM];
    __shared__ float Ws[BK][BN];

    const int tid  = threadIdx.x;
    const int row0 = blockIdx.x * BM;
    const int col0 = blockIdx.y * BN;
    const int tx   = tid % (BN / TN);
    const int ty   = tid / (BN / TN);

    const int aRow = tid / (BK / 4);
    const int aCol = (tid % (BK / 4)) * 4;
    const int wRow = tid / (BN / 4);
    const int wCol = (tid % (BN / 4)) * 4;

    ull acc2[TM][TN / 2];
#pragma unroll
    for (int i = 0; i < TM; i++)
#pragma unroll
        for (int j = 0; j < TN / 2; j++) acc2[i][j] = 0ULL;

    for (int k0 = 0; k0 < K; k0 += BK) {
#pragma unroll
        for (int r = 0; r < BM; r += 256 / (BK / 4)) {
            int gr = row0 + aRow + r;
            float4 v = make_float4(0.f, 0.f, 0.f, 0.f);
            if (gr < M)
                v = *(const float4*)(A + (size_t)gr * K + k0 + aCol);
            As[aCol + 0][aRow + r] = v.x;
            As[aCol + 1][aRow + r] = v.y;
            As[aCol + 2][aRow + r] = v.z;
            As[aCol + 3][aRow + r] = v.w;
        }
#pragma unroll
        for (int r = 0; r < BK; r += 256 / (BN / 4)) {
            *(float4*)&Ws[wRow + r][wCol] =
                *(const float4*)(W + (size_t)(k0 + wRow + r) * N + col0 + wCol);
        }
        __syncthreads();

#pragma unroll
        for (int k = 0; k < BK; k++) {
            float am[TM], wn[TN];
#pragma unroll
            for (int i = 0; i < TM; i += 4)
                *(float4*)&am[i] = *(const float4*)&As[k][ty * TM + i];
#pragma unroll
            for (int j = 0; j < TN; j += 4)
                *(float4*)&wn[j] = *(const float4*)&Ws[k][tx * TN + j];
            ull wn2[TN / 2];
#pragma unroll
            for (int j = 0; j < TN / 2; j++) wn2[j] = pk(wn[2 * j], wn[2 * j + 1]);
#pragma unroll
            for (int i = 0; i < TM; i++) {
                ull a2 = pk(am[i], am[i]);
#pragma unroll
                for (int j = 0; j < TN / 2; j++)
                    fma2(acc2[i][j], a2, wn2[j]);
            }
        }
        __syncthreads();
    }

    float bv[TN];
#pragma unroll
    for (int j = 0; j < TN; j++)
        bv[j] = HASB ? bias[col0 + tx * TN + j] : 0.f;

#pragma unroll
    for (int i = 0; i < TM; i++) {
        int gr = row0 + ty * TM + i;
        if (gr >= M) continue;
#pragma unroll
        for (int j = 0; j < TN; j += 4) {
            float t[4];
            upk(acc2[i][j / 2],     t[0], t[1]);
            upk(acc2[i][j / 2 + 1], t[2], t[3]);
#pragma unroll
            for (int q = 0; q < 4; q++) {
                float v = t[q] + bv[j + q];
                if (ACT == 1) v = v / (1.f + expf(-v)) * SSC;  // ScaledSiLU
                t[q] = v;
            }
            *(float4*)(C + (size_t)gr * N + col0 + tx * TN + j) =
                make_float4(t[0], t[1], t[2], t[3]);
        }
    }
}

// ---------------------------------------------------------------------------
// Vectorized global reduction
// ---------------------------------------------------------------------------
__device__ __forceinline__ void red4(float* p, float4 v) {
    asm volatile("red.global.add.v4.f32 [%0], {%1,%2,%3,%4};"
                 :: "l"(p), "f"(v.x), "f"(v.y), "f"(v.z), "f"(v.w)
                 : "memory");
}

// ---------------------------------------------------------------------------
// Pass A (j-sorted): rbf cols 0..255 fused with d_vec scatter.
// ef staged as duplicated (v,v) ull; inner loop reads 2 k per LDS.128 bcast.
// W slice 64KB + ef 32KB -> 2 CTAs/SM.
// ---------------------------------------------------------------------------
__global__ void __launch_bounds__(256, 2)
edge_vec_kernel(const float* __restrict__ xh, const float* __restrict__ xd,
                const float* __restrict__ vec, const float* __restrict__ efeat,
                const float* __restrict__ We, const float* __restrict__ be,
                const float* __restrict__ ev,
                const int* __restrict__ js, const int* __restrict__ is,
                const int* __restrict__ elist,
                float* __restrict__ dvec, int E)
{
    __shared__ float Ws[64 * 256];            // 64 KB
    __shared__ ull efs_all[8][EBA * 64];      // 32 KB

    const int tid = threadIdx.x;

    for (int idx = tid; idx < 64 * 64; idx += 256) {
        int k = idx >> 6, c4 = idx & 63;
        *(float4*)&Ws[k * 256 + c4 * 4] =
            *(const float4*)(We + (size_t)k * THDIM + c4 * 4);
    }
    __syncthreads();

    const int warp = tid >> 5;
    const int q    = tid & 31;
    ull* efs = efs_all[warp];

    const float4 be0 = *(const float4*)(be + 4 * q);
    const float4 be1 = *(const float4*)(be + HDIM + 4 * q);
    const float sv = IS3 * ISH;

    const int nG = E / EBA;
    const int gw = blockIdx.x * 8 + warp;
    const int stride = gridDim.x * 8;

    for (int g = gw; g < nG; g += stride) {
        const int e0 = g * EBA;

        // stage ef rows (duplicated pairs for FFMA2)
#pragma unroll
        for (int s = 0; s < EBA; s++) {
            int e = elist[e0 + s];
            float2 v = *(const float2*)(efeat + (size_t)e * FDIM + 2 * q);
            efs[s * 64 + 2 * q]     = pk(v.x, v.x);
            efs[s * 64 + 2 * q + 1] = pk(v.y, v.y);
        }
        __syncwarp();

        ull acc[EBA][4];
#pragma unroll
        for (int s = 0; s < EBA; s++)
#pragma unroll
            for (int c = 0; c < 4; c++) acc[s][c] = 0ULL;

#pragma unroll 4
        for (int k2 = 0; k2 < 32; k2++) {
            const float* wr = Ws + (k2 * 2) * 256 + 4 * q;
            ulonglong2 wa0 = *(const ulonglong2*)(wr);
            ulonglong2 wa1 = *(const ulonglong2*)(wr + 128);
            ulonglong2 wb0 = *(const ulonglong2*)(wr + 256);
            ulonglong2 wb1 = *(const ulonglong2*)(wr + 384);
#pragma unroll
            for (int s = 0; s < EBA; s++) {
                ulonglong2 ef = *(const ulonglong2*)&efs[s * 64 + k2 * 2];
                fma2(acc[s][0], ef.x, wa0.x);
                fma2(acc[s][1], ef.x, wa0.y);
                fma2(acc[s][2], ef.x, wa1.x);
                fma2(acc[s][3], ef.x, wa1.y);
                fma2(acc[s][0], ef.y, wb0.x);
                fma2(acc[s][1], ef.y, wb0.y);
                fma2(acc[s][2], ef.y, wb1.x);
                fma2(acc[s][3], ef.y, wb1.y);
            }
        }

        // epilogue: j-runs -> L1-hot gathers; atomic d_vec scatter
#pragma unroll
        for (int s = 0; s < EBA; s++) {
            const int e = elist[e0 + s];
            const int j = js[e0 + s];
            const int i = is[e0 + s];

            float r0[4], r1[4];
            upk(acc[s][0], r0[0], r0[1]); upk(acc[s][1], r0[2], r0[3]);
            upk(acc[s][2], r1[0], r1[1]); upk(acc[s][3], r1[2], r1[3]);
            r0[0] += be0.x; r0[1] += be0.y; r0[2] += be0.z; r0[3] += be0.w;
            r1[0] += be1.x; r1[1] += be1.y; r1[2] += be1.z; r1[3] += be1.w;

            const float4* xhj = (const float4*)(xh + (size_t)j * THDIM);
            const float4* xdj = (const float4*)(xd + (size_t)j * THDIM);
            const float4* xdi = (const float4*)(xd + (size_t)i * THDIM);
            const float4* vj  = (const float4*)(vec + (size_t)j * THDIM);

            float4 a0 = xhj[q],  a1 = xhj[32 + q];
            float4 b0 = xdj[q],  b1 = xdj[32 + q];
            float4 c0 = xdi[q],  c1 = xdi[32 + q];
            float4 v0 = vj[q],   v1 = vj[32 + q], v2 = vj[64 + q];

            float evd0 = ev[(size_t)e * 3 + 0];
            float evd1 = ev[(size_t)e * 3 + 1];
            float evd2 = ev[(size_t)e * 3 + 2];

            float4 m0, m1;
            m0.x = a0.x * (b0.x + c0.x) * r0[0] * sv;
            m0.y = a0.y * (b0.y + c0.y) * r0[1] * sv;
            m0.z = a0.z * (b0.z + c0.z) * r0[2] * sv;
            m0.w = a0.w * (b0.w + c0.w) * r0[3] * sv;
            m1.x = a1.x * (b1.x + c1.x) * r1[0] * sv;
            m1.y = a1.y * (b1.y + c1.y) * r1[1] * sv;
            m1.z = a1.z * (b1.z + c1.z) * r1[2] * sv;
            m1.w = a1.w * (b1.w + c1.w) * r1[3] * sv;

            float* dvb = dvec + (size_t)i * THDIM + 4 * q;
            float4 t;
            t.x = m0.x * v0.x + m1.x * evd0;
            t.y = m0.y * v0.y + m1.y * evd0;
            t.z = m0.z * v0.z + m1.z * evd0;
            t.w = m0.w * v0.w + m1.w * evd0;
            red4(dvb, t);
            t.x = m0.x * v1.x + m1.x * evd1;
            t.y = m0.y * v1.y + m1.y * evd1;
            t.z = m0.z * v1.z + m1.z * evd1;
            t.w = m0.w * v1.w + m1.w * evd1;
            red4(dvb + HDIM, t);
            t.x = m0.x * v2.x + m1.x * evd2;
            t.y = m0.y * v2.y + m1.y * evd2;
            t.z = m0.z * v2.z + m1.z * evd2;
            t.w = m0.w * v2.w + m1.w * evd2;
            red4(dvb + 2 * HDIM, t);
        }
        __syncwarp();
    }
}

// ---------------------------------------------------------------------------
// Pass B (j-sorted): rbf cols 256..383 fused with d_x scatter.
// ef staged plain float, 4 k per LDS.128 bcast + pk. 48KB -> 4 CTAs/SM.
// ---------------------------------------------------------------------------
__global__ void __launch_bounds__(256, 4)
edge_dx_kernel(const float* __restrict__ xh, const float* __restrict__ xd,
               const float* __restrict__ efeat,
               const float* __restrict__ We, const float* __restrict__ be,
               const int* __restrict__ js, const int* __restrict__ is,
               const int* __restrict__ elist,
               float* __restrict__ dx, int E)
{
    __shared__ float Ws[64 * 128];            // 32 KB
    __shared__ float efs_all[8][EBA * 64];    // 16 KB

    const int tid = threadIdx.x;

    for (int idx = tid; idx < 64 * 32; idx += 256) {
        int k = idx >> 5, c4 = idx & 31;
        *(float4*)&Ws[k * 128 + c4 * 4] =
            *(const float4*)(We + (size_t)k * THDIM + 256 + c4 * 4);
    }
    __syncthreads();

    const int warp = tid >> 5;
    const int q    = tid & 31;
    float* efs = efs_all[warp];

    const float4 be2 = *(const float4*)(be + 2 * HDIM + 4 * q);

    const int nG = E / EBA;
    const int gw = blockIdx.x * 8 + warp;
    const int stride = gridDim.x * 8;

    for (int g = gw; g < nG; g += stride) {
        const int e0 = g * EBA;

#pragma unroll
        for (int s = 0; s < EBA; s++) {
            int e = elist[e0 + s];
            float2 v = *(const float2*)(efeat + (size_t)e * FDIM + 2 * q);
            efs[s * 64 + 2 * q]     = v.x;
            efs[s * 64 + 2 * q + 1] = v.y;
        }
        __syncwarp();

        ull acc[EBA][2];
#pragma unroll
        for (int s = 0; s < EBA; s++) { acc[s][0] = 0ULL; acc[s][1] = 0ULL; }

#pragma unroll 2
        for (int k4 = 0; k4 < 16; k4++) {
            const float* wr = Ws + (k4 * 4) * 128 + 4 * q;
            ulonglong2 w0 = *(const ulonglong2*)(wr);
            ulonglong2 w1 = *(const ulonglong2*)(wr + 128);
            ulonglong2 w2 = *(const ulonglong2*)(wr + 256);
            ulonglong2 w3 = *(const ulonglong2*)(wr + 384);
#pragma unroll
            for (int s = 0; s < EBA; s++) {
                float4 efv = *(const float4*)&efs[s * 64 + k4 * 4];
                ull ea = pk(efv.x, efv.x), eb = pk(efv.y, efv.y);
                ull ec = pk(efv.z, efv.z), ed = pk(efv.w, efv.w);
                fma2(acc[s][0], ea, w0.x); fma2(acc[s][1], ea, w0.y);
                fma2(acc[s][0], eb, w1.x); fma2(acc[s][1], eb, w1.y);
                fma2(acc[s][0], ec, w2.x); fma2(acc[s][1], ec, w2.y);
                fma2(acc[s][0], ed, w3.x); fma2(acc[s][1], ed, w3.y);
            }
        }

#pragma unroll
        for (int s = 0; s < EBA; s++) {
            const int j = js[e0 + s];
            const int i = is[e0 + s];

            float r2[4];
            upk(acc[s][0], r2[0], r2[1]); upk(acc[s][1], r2[2], r2[3]);
            r2[0] += be2.x; r2[1] += be2.y; r2[2] += be2.z; r2[3] += be2.w;

            const float4* xhj = (const float4*)(xh + (size_t)j * THDIM);
            const float4* xdj = (const float4*)(xd + (size_t)j * THDIM);
            const float4* xdi = (const float4*)(xd + (size_t)i * THDIM);

            float4 a = xhj[64 + q], b = xdj[64 + q], c = xdi[64 + q];
            float4 m;
            m.x = a.x * (b.x + c.x) * r2[0] * IS3;
            m.y = a.y * (b.y + c.y) * r2[1] * IS3;
            m.z = a.z * (b.z + c.z) * r2[2] * IS3;
            m.w = a.w * (b.w + c.w) * r2[3] * IS3;

            red4(dx + (size_t)i * HDIM + 4 * q, m);
        }
        __syncwarp();
    }
}

// ---------------------------------------------------------------------------
// Vector activation epilogue
// ---------------------------------------------------------------------------
__global__ void combine_kernel(const float* __restrict__ lvec,
                               const float* __restrict__ Wg,
                               float* __restrict__ dvec, int Nn)
{
    __shared__ float wg_s[HDIM];
    __shared__ float red_s[4][3];
    int t = threadIdx.x;   // 128
    wg_s[t] = Wg[t];
    __syncthreads();

    for (int n = blockIdx.x; n < Nn; n += gridDim.x) {
        const float* vr = dvec + (size_t)n * THDIM;
        float v0 = vr[t], v1 = vr[HDIM + t], v2 = vr[2 * HDIM + t];
        float w = wg_s[t];
        float p0 = v0 * w, p1 = v1 * w, p2 = v2 * w;
#pragma unroll
        for (int off = 16; off > 0; off >>= 1) {
            p0 += __shfl_xor_sync(0xffffffffu, p0, off);
            p1 += __shfl_xor_sync(0xffffffffu, p1, off);
            p2 += __shfl_xor_sync(0xffffffffu, p2, off);
        }
        if ((t & 31) == 0) {
            red_s[t >> 5][0] = p0;
            red_s[t >> 5][1] = p1;
            red_s[t >> 5][2] = p2;
        }
        __syncthreads();
        float gv0 = red_s[0][0] + red_s[1][0] + red_s[2][0] + red_s[3][0];
        float gv1 = red_s[0][1] + red_s[1][1] + red_s[2][1] + red_s[3][1];
        float gv2 = red_s[0][2] + red_s[1][2] + red_s[2][2] + red_s[3][2];

        const float* lv = lvec + (size_t)n * THDIM;
        float l0 = lv[t], l1 = lv[HDIM + t], l2 = lv[2 * HDIM + t];
        float dot = l0 * gv0 + l1 * gv1 + l2 * gv2;

        float* o = dvec + (size_t)n * THDIM;
        if (dot >= 0.f) {
            o[t] = l0; o[HDIM + t] = l1; o[2 * HDIM + t] = l2;
        } else {
            o[t]            = (l0 + gv0) * 0.5f;
            o[HDIM + t]     = (l1 + gv1) * 0.5f;
            o[2 * HDIM + t] = (l2 + gv2) * 0.5f;
        }
        __syncthreads();
    }
}

// ---------------------------------------------------------------------------
// Launch: 3-stream DAG schedule (graph-capture-safe via events)
//   s0: xd gemm ----------------------------\
//   sC: zero(d_out) -> h1 -> xh ------------- join -> edge_vec -> lvec -> combine
//   sB: CSR build ---------------------------/     \-> edge_dx (sB, overlapped)
// ---------------------------------------------------------------------------
extern "C" void kernel_launch(void* const* d_in, const int* in_sizes, int n_in,
                              void* d_out, int out_size)
{
    const float* x     = (const float*)d_in[0];
    const float* xdef  = (const float*)d_in[1];
    const float* vec   = (const float*)d_in[2];
    const float* efeat = (const float*)d_in[3];
    const float* evec  = (const float*)d_in[4];
    const int*   eidx  = (const int*)  d_in[5];
    const float* Wd    = (const float*)d_in[6];
    const float* bd    = (const float*)d_in[7];
    const float* W1    = (const float*)d_in[8];
    const float* b1    = (const float*)d_in[9];
    const float* W2    = (const float*)d_in[10];
    const float* b2    = (const float*)d_in[11];
    const float* We    = (const float*)d_in[12];
    const float* be    = (const float*)d_in[13];
    const float* Wl    = (const float*)d_in[14];
    const float* Wg    = (const float*)d_in[15];

    int N = in_sizes[0] / HDIM;     // 50000
    int E = in_sizes[4] / 3;        // 400000

    float *p_xd, *p_h1, *p_xh, *p_lvec;
    int *p_deg, *p_cur, *p_bsum, *p_boff, *p_elist, *p_js, *p_is;
    cudaGetSymbolAddress((void**)&p_xd,    g_xd);
    cudaGetSymbolAddress((void**)&p_h1,    g_h1);
    cudaGetSymbolAddress((void**)&p_xh,    g_xh);
    cudaGetSymbolAddress((void**)&p_lvec,  g_lvec);
    cudaGetSymbolAddress((void**)&p_deg,   g_deg);
    cudaGetSymbolAddress((void**)&p_cur,   g_cur);
    cudaGetSymbolAddress((void**)&p_bsum,  g_bsum);
    cudaGetSymbolAddress((void**)&p_boff,  g_boff);
    cudaGetSymbolAddress((void**)&p_elist, g_elist);
    cudaGetSymbolAddress((void**)&p_js,    g_js);
    cudaGetSymbolAddress((void**)&p_is,    g_is);

    float* dx   = (float*)d_out;
    float* dvec = (float*)d_out + (size_t)N * HDIM;

    const int* ej = eidx;
    const int* ei = eidx + E;

    cudaStream_t s0 = 0;   // legacy default stream (capture origin)
    cudaStream_t sB, sC;
    cudaStreamCreateWithFlags(&sB, cudaStreamNonBlocking);
    cudaStreamCreateWithFlags(&sC, cudaStreamNonBlocking);
    cudaEvent_t evFork, evCSR, evC, evJoin, evB;
    cudaEventCreateWithFlags(&evFork, cudaEventDisableTiming);
    cudaEventCreateWithFlags(&evCSR,  cudaEventDisableTiming);
    cudaEventCreateWithFlags(&evC,    cudaEventDisableTiming);
    cudaEventCreateWithFlags(&evJoin, cudaEventDisableTiming);
    cudaEventCreateWithFlags(&evB,    cudaEventDisableTiming);

    // ---- fork: CSR on sB, zero+h1+xh on sC, xd on s0 -----------------------
    cudaEventRecord(evFork, s0);
    cudaStreamWaitEvent(sB, evFork, 0);
    cudaStreamWaitEvent(sC, evFork, 0);

    // sB: CSR build (counting sort by source j)
    int nb = (N + 255) / 256;
    zeroi_kernel<<<(N + 255) / 256, 256, 0, sB>>>(p_deg, N);
    hist_kernel<<<(E + 255) / 256, 256, 0, sB>>>(ej, p_deg, E);
    scan1_kernel<<<nb, 256, 0, sB>>>(p_deg, p_bsum, N);
    scan2_kernel<<<1, 256, 0, sB>>>(p_bsum, p_boff, nb);
    scan3_kernel<<<nb, 256, 0, sB>>>(p_deg, p_boff, p_cur, N);
    fill_kernel<<<(E + 255) / 256, 256, 0, sB>>>(ej, ei, p_cur, p_elist,
                                                 p_js, p_is, E);
    cudaEventRecord(evCSR, sB);

    dim3 gN((N + 127) / 128, 3);
    dim3 gN1((N + 127) / 128, 1);
    dim3 gL((3 * N + 127) / 128, 1);

    // sC: zero d_out, then h1 -> xh chain
    long n4 = (long)out_size / 4;
    zero_kernel<<<(unsigned)((n4 + 255) / 256), 256, 0, sC>>>((float4*)d_out, n4);
    sgemm_kernel<128, 64,16,8,4,1,1><<<gN1,256, 0, sC>>>(x, W1, b1, p_h1, N, FDIM, HDIM);
    sgemm_kernel<128,128,16,8,8,0,1><<<gN, 256, 0, sC>>>(p_h1, W2, b2, p_xh, N, THDIM, FDIM);
    cudaEventRecord(evC, sC);

    // s0: xd gemm (concurrent with sC's chain)
    sgemm_kernel<128,128,16,8,8,0,1><<<gN, 256, 0, s0>>>(xdef, Wd, bd, p_xd, N, THDIM, HDIM);

    // join: s0 waits for CSR + (zero, h1, xh)
    cudaStreamWaitEvent(s0, evCSR, 0);
    cudaStreamWaitEvent(s0, evC, 0);

    // ---- fork 2: edge_dx on sB (overlaps edge_vec + lvec + combine) --------
    cudaEventRecord(evJoin, s0);
    cudaStreamWaitEvent(sB, evJoin, 0);
    edge_dx_kernel<<<592, 256, 0, sB>>>(p_xh, p_xd, efeat, We, be,
                                        p_js, p_is, p_elist, dx, E);
    cudaEventRecord(evB, sB);

    // main: pass A -> lvec -> combine
    edge_vec_kernel<<<296, 256, 0, s0>>>(p_xh, p_xd, vec, efeat, We, be, evec,
                                         p_js, p_is, p_elist, dvec, E);
    sgemm_kernel<128,128,16,8,8,0,0><<<gL, 256, 0, s0>>>(dvec, Wl, nullptr,
                                                          p_lvec, 3 * N, HDIM, HDIM);
    combine_kernel<<<2048, 128, 0, s0>>>(p_lvec, Wg, dvec, N);

    // ---- join pass B back into main ----------------------------------------
    cudaStreamWaitEvent(s0, evB, 0);

    cudaEventDestroy(evFork);
    cudaEventDestroy(evCSR);
    cudaEventDestroy(evC);
    cudaEventDestroy(evJoin);
    cudaEventDestroy(evB);
    cudaStreamDestroy(sB);
    cudaStreamDestroy(sC);
}

// round 15
// speedup vs baseline: 1.0409x; 1.0409x over previous
#include <cuda_runtime.h>
#include <stdint.h>
#include <math.h>

// Problem constants
#define HDIM 128
#define FDIM 64
#define THDIM 384              // 3*H
#define IS3  0.5773502691896258f      // 1/sqrt(3)
#define ISH  0.08838834764831845f     // 1/sqrt(128)
#define SSC  1.6666666666666667f      // 1/0.6

#define MAXN 50000
#define MAXE 400000
#define EBA 8                  // edges per warp-group

typedef unsigned long long ull;

// Scratch (device globals: allocation-free)
__device__ float g_xd  [MAXN * THDIM];
__device__ float g_h1  [MAXN * FDIM];
__device__ float g_xh  [MAXN * THDIM];
__device__ float g_lvec[MAXN * 3 * HDIM];
__device__ int   g_deg [MAXN];
__device__ int   g_cur [MAXN];
__device__ int   g_bsum[256];
__device__ int   g_boff[256];
__device__ int   g_elist[MAXE];
__device__ int   g_js  [MAXE];
__device__ int   g_is  [MAXE];

// ---------------------------------------------------------------------------
// Packed fp32x2 helpers (FFMA2 — ptxas never auto-fuses)
// ---------------------------------------------------------------------------
__device__ __forceinline__ ull pk(float lo, float hi) {
    ull r; asm("mov.b64 %0, {%1, %2};" : "=l"(r) : "f"(lo), "f"(hi)); return r;
}
__device__ __forceinline__ void upk(ull v, float& lo, float& hi) {
    asm("mov.b64 {%0, %1}, %2;" : "=f"(lo), "=f"(hi) : "l"(v));
}
__device__ __forceinline__ void fma2(ull& d, ull a, ull b) {
    asm("fma.rn.f32x2 %0, %1, %2, %0;" : "+l"(d) : "l"(a), "l"(b));
}

// ---------------------------------------------------------------------------
// Utility + CSR build (counting sort by source j)
// ---------------------------------------------------------------------------
__global__ void zero_kernel(float4* __restrict__ p, long n4) {
    long i = (long)blockIdx.x * blockDim.x + threadIdx.x;
    if (i < n4) p[i] = make_float4(0.f, 0.f, 0.f, 0.f);
}
__global__ void zeroi_kernel(int* __restrict__ p, int n) {
    int i = blockIdx.x * blockDim.x + threadIdx.x;
    if (i < n) p[i] = 0;
}
__global__ void hist_kernel(const int* __restrict__ key, int* __restrict__ deg, int E) {
    int e = blockIdx.x * blockDim.x + threadIdx.x;
    if (e < E) atomicAdd(&deg[key[e]], 1);
}
__global__ void scan1_kernel(const int* __restrict__ deg, int* __restrict__ bsum, int Nn) {
    __shared__ int s[256];
    int t = threadIdx.x;
    int idx = blockIdx.x * 256 + t;
    s[t] = (idx < Nn) ? deg[idx] : 0;
    __syncthreads();
#pragma unroll
    for (int d = 128; d > 0; d >>= 1) {
        if (t < d) s[t] += s[t + d];
        __syncthreads();
    }
    if (t == 0) bsum[blockIdx.x] = s[0];
}
__global__ void scan2_kernel(const int* __restrict__ bsum, int* __restrict__ boff, int nb) {
    __shared__ int s[256];
    int t = threadIdx.x;
    s[t] = (t < nb) ? bsum[t] : 0;
    __syncthreads();
#pragma unroll
    for (int d = 1; d < 256; d <<= 1) {
        int v = (t >= d) ? s[t - d] : 0;
        __syncthreads();
        s[t] += v;
        __syncthreads();
    }
    if (t < nb) boff[t] = (t == 0) ? 0 : s[t - 1];
}
__global__ void scan3_kernel(const int* __restrict__ deg, const int* __restrict__ boff,
                             int* __restrict__ cur, int Nn) {
    __shared__ int s[256];
    int t = threadIdx.x;
    int idx = blockIdx.x * 256 + t;
    int v = (idx < Nn) ? deg[idx] : 0;
    s[t] = v;
    __syncthreads();
#pragma unroll
    for (int d = 1; d < 256; d <<= 1) {
        int x = (t >= d) ? s[t - d] : 0;
        __syncthreads();
        s[t] += x;
        __syncthreads();
    }
    if (idx < Nn)
        cur[idx] = boff[blockIdx.x] + s[t] - v;
}
__global__ void fill_kernel(const int* __restrict__ ej, const int* __restrict__ ei,
                            int* __restrict__ cursor, int* __restrict__ elist,
                            int* __restrict__ js, int* __restrict__ is, int E) {
    int e = blockIdx.x * blockDim.x + threadIdx.x;
    if (e < E) {
        int j = ej[e];
        int slot = atomicAdd(&cursor[j], 1);
        elist[slot] = e;
        js[slot] = j;
        is[slot] = ei[e];
    }
}

// ---------------------------------------------------------------------------
// fp32 SGEMM with FFMA2 inner product: C = act(A @ W + bias)
// ---------------------------------------------------------------------------
template<int BM, int BN, int BK, int TM, int TN, int ACT, int HASB>
__global__ void __launch_bounds__(256)
sgemm_kernel(const float* __restrict__ A, const float* __restrict__ W,
             const float* __restrict__ bias, float* __restrict__ C,
             int M, int N, int K)
{
    __shared__ float As[BK][BM];
    __shared__ float Ws[BK][BN];

    const int tid  = threadIdx.x;
    const int row0 = blockIdx.x * BM;
    const int col0 = blockIdx.y * BN;
    const int tx   = tid % (BN / TN);
    const int ty   = tid / (BN / TN);

    const int aRow = tid / (BK / 4);
    const int aCol = (tid % (BK / 4)) * 4;
    const int wRow = tid / (BN / 4);
    const int wCol = (tid % (BN / 4)) * 4;

    ull acc2[TM][TN / 2];
#pragma unroll
    for (int i = 0; i < TM; i++)
#pragma unroll
        for (int j = 0; j < TN / 2; j++) acc2[i][j] = 0ULL;

    for (int k0 = 0; k0 < K; k0 += BK) {
#pragma unroll
        for (int r = 0; r < BM; r += 256 / (BK / 4)) {
            int gr = row0 + aRow + r;
            float4 v = make_float4(0.f, 0.f, 0.f, 0.f);
            if (gr < M)
                v = *(const float4*)(A + (size_t)gr * K + k0 + aCol);
            As[aCol + 0][aRow + r] = v.x;
            As[aCol + 1][aRow + r] = v.y;
            As[aCol + 2][aRow + r] = v.z;
            As[aCol + 3][aRow + r] = v.w;
        }
#pragma unroll
        for (int r = 0; r < BK; r += 256 / (BN / 4)) {
            *(float4*)&Ws[wRow + r][wCol] =
                *(const float4*)(W + (size_t)(k0 + wRow + r) * N + col0 + wCol);
        }
        __syncthreads();

#pragma unroll
        for (int k = 0; k < BK; k++) {
            float am[TM], wn[TN];
#pragma unroll
            for (int i = 0; i < TM; i += 4)
                *(float4*)&am[i] = *(const float4*)&As[k][ty * TM + i];
#pragma unroll
            for (int j = 0; j < TN; j += 4)
                *(float4*)&wn[j] = *(const float4*)&Ws[k][tx * TN + j];
            ull wn2[TN / 2];
#pragma unroll
            for (int j = 0; j < TN / 2; j++) wn2[j] = pk(wn[2 * j], wn[2 * j + 1]);
#pragma unroll
            for (int i = 0; i < TM; i++) {
                ull a2 = pk(am[i], am[i]);
#pragma unroll
                for (int j = 0; j < TN / 2; j++)
                    fma2(acc2[i][j], a2, wn2[j]);
            }
        }
        __syncthreads();
    }

    float bv[TN];
#pragma unroll
    for (int j = 0; j < TN; j++)
        bv[j] = HASB ? bias[col0 + tx * TN + j] : 0.f;

#pragma unroll
    for (int i = 0; i < TM; i++) {
        int gr = row0 + ty * TM + i;
        if (gr >= M) continue;
#pragma unroll
        for (int j = 0; j < TN; j += 4) {
            float t[4];
            upk(acc2[i][j / 2],     t[0], t[1]);
            upk(acc2[i][j / 2 + 1], t[2], t[3]);
#pragma unroll
            for (int q = 0; q < 4; q++) {
                float v = t[q] + bv[j + q];
                if (ACT == 1) v = v / (1.f + expf(-v)) * SSC;  // ScaledSiLU
                t[q] = v;
            }
            *(float4*)(C + (size_t)gr * N + col0 + tx * TN + j) =
                make_float4(t[0], t[1], t[2], t[3]);
        }
    }
}

// ---------------------------------------------------------------------------
// Vectorized global reduction
// ---------------------------------------------------------------------------
__device__ __forceinline__ void red4(float* p, float4 v) {
    asm volatile("red.global.add.v4.f32 [%0], {%1,%2,%3,%4};"
                 :: "l"(p), "f"(v.x), "f"(v.y), "f"(v.z), "f"(v.w)
                 : "memory");
}

// ---------------------------------------------------------------------------
// Pass A (j-sorted): rbf cols 0..255 fused with d_vec scatter.
// ef staged as duplicated (v,v) ull; inner loop reads 2 k per LDS.128 bcast.
// W slice 64KB + ef 32KB -> 2 CTAs/SM.
// ---------------------------------------------------------------------------
__global__ void __launch_bounds__(256, 2)
edge_vec_kernel(const float* __restrict__ xh, const float* __restrict__ xd,
                const float* __restrict__ vec, const float* __restrict__ efeat,
                const float* __restrict__ We, const float* __restrict__ be,
                const float* __restrict__ ev,
                const int* __restrict__ js, const int* __restrict__ is,
                const int* __restrict__ elist,
                float* __restrict__ dvec, int E)
{
    __shared__ float Ws[64 * 256];            // 64 KB
    __shared__ ull efs_all[8][EBA * 64];      // 32 KB

    const int tid = threadIdx.x;

    for (int idx = tid; idx < 64 * 64; idx += 256) {
        int k = idx >> 6, c4 = idx & 63;
        *(float4*)&Ws[k * 256 + c4 * 4] =
            *(const float4*)(We + (size_t)k * THDIM + c4 * 4);
    }
    __syncthreads();

    const int warp = tid >> 5;
    const int q    = tid & 31;
    ull* efs = efs_all[warp];

    const float4 be0 = *(const float4*)(be + 4 * q);
    const float4 be1 = *(const float4*)(be + HDIM + 4 * q);
    const float sv = IS3 * ISH;

    const int nG = E / EBA;
    const int gw = blockIdx.x * 8 + warp;
    const int stride = gridDim.x * 8;

    for (int g = gw; g < nG; g += stride) {
        const int e0 = g * EBA;

        // stage ef rows (duplicated pairs for FFMA2)
#pragma unroll
        for (int s = 0; s < EBA; s++) {
            int e = elist[e0 + s];
            float2 v = *(const float2*)(efeat + (size_t)e * FDIM + 2 * q);
            efs[s * 64 + 2 * q]     = pk(v.x, v.x);
            efs[s * 64 + 2 * q + 1] = pk(v.y, v.y);
        }
        __syncwarp();

        ull acc[EBA][4];
#pragma unroll
        for (int s = 0; s < EBA; s++)
#pragma unroll
            for (int c = 0; c < 4; c++) acc[s][c] = 0ULL;

#pragma unroll 4
        for (int k2 = 0; k2 < 32; k2++) {
            const float* wr = Ws + (k2 * 2) * 256 + 4 * q;
            ulonglong2 wa0 = *(const ulonglong2*)(wr);
            ulonglong2 wa1 = *(const ulonglong2*)(wr + 128);
            ulonglong2 wb0 = *(const ulonglong2*)(wr + 256);
            ulonglong2 wb1 = *(const ulonglong2*)(wr + 384);
#pragma unroll
            for (int s = 0; s < EBA; s++) {
                ulonglong2 ef = *(const ulonglong2*)&efs[s * 64 + k2 * 2];
                fma2(acc[s][0], ef.x, wa0.x);
                fma2(acc[s][1], ef.x, wa0.y);
                fma2(acc[s][2], ef.x, wa1.x);
                fma2(acc[s][3], ef.x, wa1.y);
                fma2(acc[s][0], ef.y, wb0.x);
                fma2(acc[s][1], ef.y, wb0.y);
                fma2(acc[s][2], ef.y, wb1.x);
                fma2(acc[s][3], ef.y, wb1.y);
            }
        }

        // epilogue: j-runs -> L1-hot gathers; atomic d_vec scatter
#pragma unroll
        for (int s = 0; s < EBA; s++) {
            const int e = elist[e0 + s];
            const int j = js[e0 + s];
            const int i = is[e0 + s];

            float r0[4], r1[4];
            upk(acc[s][0], r0[0], r0[1]); upk(acc[s][1], r0[2], r0[3]);
            upk(acc[s][2], r1[0], r1[1]); upk(acc[s][3], r1[2], r1[3]);
            r0[0] += be0.x; r0[1] += be0.y; r0[2] += be0.z; r0[3] += be0.w;
            r1[0] += be1.x; r1[1] += be1.y; r1[2] += be1.z; r1[3] += be1.w;

            const float4* xhj = (const float4*)(xh + (size_t)j * THDIM);
            const float4* xdj = (const float4*)(xd + (size_t)j * THDIM);
            const float4* xdi = (const float4*)(xd + (size_t)i * THDIM);
            const float4* vj  = (const float4*)(vec + (size_t)j * THDIM);

            float4 a0 = xhj[q],  a1 = xhj[32 + q];
            float4 b0 = xdj[q],  b1 = xdj[32 + q];
            float4 c0 = xdi[q],  c1 = xdi[32 + q];
            float4 v0 = vj[q],   v1 = vj[32 + q], v2 = vj[64 + q];

            float evd0 = ev[(size_t)e * 3 + 0];
            float evd1 = ev[(size_t)e * 3 + 1];
            float evd2 = ev[(size_t)e * 3 + 2];

            float4 m0, m1;
            m0.x = a0.x * (b0.x + c0.x) * r0[0] * sv;
            m0.y = a0.y * (b0.y + c0.y) * r0[1] * sv;
            m0.z = a0.z * (b0.z + c0.z) * r0[2] * sv;
            m0.w = a0.w * (b0.w + c0.w) * r0[3] * sv;
            m1.x = a1.x * (b1.x + c1.x) * r1[0] * sv;
            m1.y = a1.y * (b1.y + c1.y) * r1[1] * sv;
            m1.z = a1.z * (b1.z + c1.z) * r1[2] * sv;
            m1.w = a1.w * (b1.w + c1.w) * r1[3] * sv;

            float* dvb = dvec + (size_t)i * THDIM + 4 * q;
            float4 t;
            t.x = m0.x * v0.x + m1.x * evd0;
            t.y = m0.y * v0.y + m1.y * evd0;
            t.z = m0.z * v0.z + m1.z * evd0;
            t.w = m0.w * v0.w + m1.w * evd0;
            red4(dvb, t);
            t.x = m0.x * v1.x + m1.x * evd1;
            t.y = m0.y * v1.y + m1.y * evd1;
            t.z = m0.z * v1.z + m1.z * evd1;
            t.w = m0.w * v1.w + m1.w * evd1;
            red4(dvb + HDIM, t);
            t.x = m0.x * v2.x + m1.x * evd2;
            t.y = m0.y * v2.y + m1.y * evd2;
            t.z = m0.z * v2.z + m1.z * evd2;
            t.w = m0.w * v2.w + m1.w * evd2;
            red4(dvb + 2 * HDIM, t);
        }
        __syncwarp();
    }
}

// ---------------------------------------------------------------------------
// Pass B (j-sorted): rbf cols 256..383 fused with d_x scatter.
// ef staged plain float, 4 k per LDS.128 bcast + pk. 48KB -> 4 CTAs/SM.
// ---------------------------------------------------------------------------
__global__ void __launch_bounds__(256, 4)
edge_dx_kernel(const float* __restrict__ xh, const float* __restrict__ xd,
               const float* __restrict__ efeat,
               const float* __restrict__ We, const float* __restrict__ be,
               const int* __restrict__ js, const int* __restrict__ is,
               const int* __restrict__ elist,
               float* __restrict__ dx, int E)
{
    __shared__ float Ws[64 * 128];            // 32 KB
    __shared__ float efs_all[8][EBA * 64];    // 16 KB

    const int tid = threadIdx.x;

    for (int idx = tid; idx < 64 * 32; idx += 256) {
        int k = idx >> 5, c4 = idx & 31;
        *(float4*)&Ws[k * 128 + c4 * 4] =
            *(const float4*)(We + (size_t)k * THDIM + 256 + c4 * 4);
    }
    __syncthreads();

    const int warp = tid >> 5;
    const int q    = tid & 31;
    float* efs = efs_all[warp];

    const float4 be2 = *(const float4*)(be + 2 * HDIM + 4 * q);

    const int nG = E / EBA;
    const int gw = blockIdx.x * 8 + warp;
    const int stride = gridDim.x * 8;

    for (int g = gw; g < nG; g += stride) {
        const int e0 = g * EBA;

#pragma unroll
        for (int s = 0; s < EBA; s++) {
            int e = elist[e0 + s];
            float2 v = *(const float2*)(efeat + (size_t)e * FDIM + 2 * q);
            efs[s * 64 + 2 * q]     = v.x;
            efs[s * 64 + 2 * q + 1] = v.y;
        }
        __syncwarp();

        ull acc[EBA][2];
#pragma unroll
        for (int s = 0; s < EBA; s++) { acc[s][0] = 0ULL; acc[s][1] = 0ULL; }

#pragma unroll 2
        for (int k4 = 0; k4 < 16; k4++) {
            const float* wr = Ws + (k4 * 4) * 128 + 4 * q;
            ulonglong2 w0 = *(const ulonglong2*)(wr);
            ulonglong2 w1 = *(const ulonglong2*)(wr + 128);
            ulonglong2 w2 = *(const ulonglong2*)(wr + 256);
            ulonglong2 w3 = *(const ulonglong2*)(wr + 384);
#pragma unroll
            for (int s = 0; s < EBA; s++) {
                float4 efv = *(const float4*)&efs[s * 64 + k4 * 4];
                ull ea = pk(efv.x, efv.x), eb = pk(efv.y, efv.y);
                ull ec = pk(efv.z, efv.z), ed = pk(efv.w, efv.w);
                fma2(acc[s][0], ea, w0.x); fma2(acc[s][1], ea, w0.y);
                fma2(acc[s][0], eb, w1.x); fma2(acc[s][1], eb, w1.y);
                fma2(acc[s][0], ec, w2.x); fma2(acc[s][1], ec, w2.y);
                fma2(acc[s][0], ed, w3.x); fma2(acc[s][1], ed, w3.y);
            }
        }

#pragma unroll
        for (int s = 0; s < EBA; s++) {
            const int j = js[e0 + s];
            const int i = is[e0 + s];

            float r2[4];
            upk(acc[s][0], r2[0], r2[1]); upk(acc[s][1], r2[2], r2[3]);
            r2[0] += be2.x; r2[1] += be2.y; r2[2] += be2.z; r2[3] += be2.w;

            const float4* xhj = (const float4*)(xh + (size_t)j * THDIM);
            const float4* xdj = (const float4*)(xd + (size_t)j * THDIM);
            const float4* xdi = (const float4*)(xd + (size_t)i * THDIM);

            float4 a = xhj[64 + q], b = xdj[64 + q], c = xdi[64 + q];
            float4 m;
            m.x = a.x * (b.x + c.x) * r2[0] * IS3;
            m.y = a.y * (b.y + c.y) * r2[1] * IS3;
            m.z = a.z * (b.z + c.z) * r2[2] * IS3;
            m.w = a.w * (b.w + c.w) * r2[3] * IS3;

            red4(dx + (size_t)i * HDIM + 4 * q, m);
        }
        __syncwarp();
    }
}

// ---------------------------------------------------------------------------
// Vector activation epilogue
// ---------------------------------------------------------------------------
__global__ void combine_kernel(const float* __restrict__ lvec,
                               const float* __restrict__ Wg,
                               float* __restrict__ dvec, int Nn)
{
    __shared__ float wg_s[HDIM];
    __shared__ float red_s[4][3];
    int t = threadIdx.x;   // 128
    wg_s[t] = Wg[t];
    __syncthreads();

    for (int n = blockIdx.x; n < Nn; n += gridDim.x) {
        const float* vr = dvec + (size_t)n * THDIM;
        float v0 = vr[t], v1 = vr[HDIM + t], v2 = vr[2 * HDIM + t];
        float w = wg_s[t];
        float p0 = v0 * w, p1 = v1 * w, p2 = v2 * w;
#pragma unroll
        for (int off = 16; off > 0; off >>= 1) {
            p0 += __shfl_xor_sync(0xffffffffu, p0, off);
            p1 += __shfl_xor_sync(0xffffffffu, p1, off);
            p2 += __shfl_xor_sync(0xffffffffu, p2, off);
        }
        if ((t & 31) == 0) {
            red_s[t >> 5][0] = p0;
            red_s[t >> 5][1] = p1;
            red_s[t >> 5][2] = p2;
        }
        __syncthreads();
        float gv0 = red_s[0][0] + red_s[1][0] + red_s[2][0] + red_s[3][0];
        float gv1 = red_s[0][1] + red_s[1][1] + red_s[2][1] + red_s[3][1];
        float gv2 = red_s[0][2] + red_s[1][2] + red_s[2][2] + red_s[3][2];

        const float* lv = lvec + (size_t)n * THDIM;
        float l0 = lv[t], l1 = lv[HDIM + t], l2 = lv[2 * HDIM + t];
        float dot = l0 * gv0 + l1 * gv1 + l2 * gv2;

        float* o = dvec + (size_t)n * THDIM;
        if (dot >= 0.f) {
            o[t] = l0; o[HDIM + t] = l1; o[2 * HDIM + t] = l2;
        } else {
            o[t]            = (l0 + gv0) * 0.5f;
            o[HDIM + t]     = (l1 + gv1) * 0.5f;
            o[2 * HDIM + t] = (l2 + gv2) * 0.5f;
        }
        __syncthreads();
    }
}

// ---------------------------------------------------------------------------
// Launch: DAG schedule (graph-capture-safe via events)
//   sB: zero(d_out) -> CSR build -----------------\
//   sC: h1 gemm (small) ----------\               |
//   s0: xd gemm -> (wait h1) xh --- (wait CSR) join -> edge_vec -> lvec -> combine
//                                                \-> edge_dx (sB, overlapped)
// ---------------------------------------------------------------------------
extern "C" void kernel_launch(void* const* d_in, const int* in_sizes, int n_in,
                              void* d_out, int out_size)
{
    const float* x     = (const float*)d_in[0];
    const float* xdef  = (const float*)d_in[1];
    const float* vec   = (const float*)d_in[2];
    const float* efeat = (const float*)d_in[3];
    const float* evec  = (const float*)d_in[4];
    const int*   eidx  = (const int*)  d_in[5];
    const float* Wd    = (const float*)d_in[6];
    const float* bd    = (const float*)d_in[7];
    const float* W1    = (const float*)d_in[8];
    const float* b1    = (const float*)d_in[9];
    const float* W2    = (const float*)d_in[10];
    const float* b2    = (const float*)d_in[11];
    const float* We    = (const float*)d_in[12];
    const float* be    = (const float*)d_in[13];
    const float* Wl    = (const float*)d_in[14];
    const float* Wg    = (const float*)d_in[15];

    int N = in_sizes[0] / HDIM;     // 50000
    int E = in_sizes[4] / 3;        // 400000

    float *p_xd, *p_h1, *p_xh, *p_lvec;
    int *p_deg, *p_cur, *p_bsum, *p_boff, *p_elist, *p_js, *p_is;
    cudaGetSymbolAddress((void**)&p_xd,    g_xd);
    cudaGetSymbolAddress((void**)&p_h1,    g_h1);
    cudaGetSymbolAddress((void**)&p_xh,    g_xh);
    cudaGetSymbolAddress((void**)&p_lvec,  g_lvec);
    cudaGetSymbolAddress((void**)&p_deg,   g_deg);
    cudaGetSymbolAddress((void**)&p_cur,   g_cur);
    cudaGetSymbolAddress((void**)&p_bsum,  g_bsum);
    cudaGetSymbolAddress((void**)&p_boff,  g_boff);
    cudaGetSymbolAddress((void**)&p_elist, g_elist);
    cudaGetSymbolAddress((void**)&p_js,    g_js);
    cudaGetSymbolAddress((void**)&p_is,    g_is);

    float* dx   = (float*)d_out;
    float* dvec = (float*)d_out + (size_t)N * HDIM;

    const int* ej = eidx;
    const int* ei = eidx + E;

    cudaStream_t s0 = 0;   // legacy default stream (capture origin)
    cudaStream_t sB, sC;
    cudaStreamCreateWithFlags(&sB, cudaStreamNonBlocking);
    cudaStreamCreateWithFlags(&sC, cudaStreamNonBlocking);
    cudaEvent_t evFork, evCSR, evH, evJoin, evB;
    cudaEventCreateWithFlags(&evFork, cudaEventDisableTiming);
    cudaEventCreateWithFlags(&evCSR,  cudaEventDisableTiming);
    cudaEventCreateWithFlags(&evH,    cudaEventDisableTiming);
    cudaEventCreateWithFlags(&evJoin, cudaEventDisableTiming);
    cudaEventCreateWithFlags(&evB,    cudaEventDisableTiming);

    // ---- fork ---------------------------------------------------------------
    cudaEventRecord(evFork, s0);
    cudaStreamWaitEvent(sB, evFork, 0);
    cudaStreamWaitEvent(sC, evFork, 0);

    // sB: zero d_out (memory-bound, independent) + CSR build
    long n4 = (long)out_size / 4;
    zero_kernel<<<(unsigned)((n4 + 255) / 256), 256, 0, sB>>>((float4*)d_out, n4);
    int nb = (N + 255) / 256;
    zeroi_kernel<<<(N + 255) / 256, 256, 0, sB>>>(p_deg, N);
    hist_kernel<<<(E + 255) / 256, 256, 0, sB>>>(ej, p_deg, E);
    scan1_kernel<<<nb, 256, 0, sB>>>(p_deg, p_bsum, N);
    scan2_kernel<<<1, 256, 0, sB>>>(p_bsum, p_boff, nb);
    scan3_kernel<<<nb, 256, 0, sB>>>(p_deg, p_boff, p_cur, N);
    fill_kernel<<<(E + 255) / 256, 256, 0, sB>>>(ej, ei, p_cur, p_elist,
                                                 p_js, p_is, E);
    cudaEventRecord(evCSR, sB);

    dim3 gN((N + 127) / 128, 3);
    dim3 gN1((N + 127) / 128, 1);
    dim3 gL((3 * N + 127) / 128, 1);

    // sC: small h1 gemm (overlaps xd on s0)
    sgemm_kernel<128, 64,16,8,4,1,1><<<gN1,256, 0, sC>>>(x, W1, b1, p_h1, N, FDIM, HDIM);
    cudaEventRecord(evH, sC);

    // s0: xd gemm, then xh (after h1 ready)
    sgemm_kernel<128,128,16,8,8,0,1><<<gN, 256, 0, s0>>>(xdef, Wd, bd, p_xd, N, THDIM, HDIM);
    cudaStreamWaitEvent(s0, evH, 0);
    sgemm_kernel<128,128,16,8,8,0,1><<<gN, 256, 0, s0>>>(p_h1, W2, b2, p_xh, N, THDIM, FDIM);

    // join CSR (incl. zero of d_out) into main before edge passes
    cudaStreamWaitEvent(s0, evCSR, 0);

    // ---- fork 2: edge_dx on sB (overlaps edge_vec + lvec + combine) --------
    cudaEventRecord(evJoin, s0);
    cudaStreamWaitEvent(sB, evJoin, 0);
    edge_dx_kernel<<<592, 256, 0, sB>>>(p_xh, p_xd, efeat, We, be,
                                        p_js, p_is, p_elist, dx, E);
    cudaEventRecord(evB, sB);

    // main: pass A -> lvec -> combine
    edge_vec_kernel<<<296, 256, 0, s0>>>(p_xh, p_xd, vec, efeat, We, be, evec,
                                         p_js, p_is, p_elist, dvec, E);
    sgemm_kernel<128,128,16,8,8,0,0><<<gL, 256, 0, s0>>>(dvec, Wl, nullptr,
                                                          p_lvec, 3 * N, HDIM, HDIM);
    combine_kernel<<<2048, 128, 0, s0>>>(p_lvec, Wg, dvec, N);

    // ---- join pass B back into main ----------------------------------------
    cudaStreamWaitEvent(s0, evB, 0);

    cudaEventDestroy(evFork);
    cudaEventDestroy(evCSR);
    cudaEventDestroy(evH);
    cudaEventDestroy(evJoin);
    cudaEventDestroy(evB);
    cudaStreamDestroy(sB);
    cudaStreamDestroy(sC);
}